// round 3
// baseline (speedup 1.0000x reference)
#include <cuda_runtime.h>
#include <cstdint>
#include <math.h>

#define T_STEPS 512
#define NBATCH  256
#define IN_DIM  300
#define HID     256

// 134 MB scratch for the precomputed input projection xp[t][b][h]
__device__ float g_xp[T_STEPS * NBATCH * HID];

// ---------------------------------------------------------------------------
// packed f32x2 FMA helpers (ptxas never emits FFMA2 from C++; PTX-only)
// ---------------------------------------------------------------------------
__device__ __forceinline__ void fma2(unsigned long long& d,
                                     unsigned long long a,
                                     unsigned long long b) {
    asm("fma.rn.f32x2 %0, %1, %2, %0;" : "+l"(d) : "l"(a), "l"(b));
}
__device__ __forceinline__ float hsum2(unsigned long long v) {
    float lo = __uint_as_float((unsigned)v);
    float hi = __uint_as_float((unsigned)(v >> 32));
    return lo + hi;
}
__device__ __forceinline__ float fast_tanh(float z) {
    // tanh(z) = 1 - 2/(exp(2z)+1); exp overflow -> fdividef returns 0 -> 1.0 (correct)
    float e = __expf(2.0f * z);
    return 1.0f - __fdividef(2.0f, e + 1.0f);
}

// ---------------------------------------------------------------------------
// Kernel 1: xp[m][h] = x[m][:] . W_ih[h][:] + b_ih[h] + b_hh[h]
// M = 131072, K = 300 (pad-masked to 320), N = 256. fp32 with f32x2 K-packing.
// BM=128, BN=64, 256 threads, thread tile 8m x 4n.
// ---------------------------------------------------------------------------
#define GA_BM 128
#define GA_BN 64
#define XS_STRIDE 36   // 32 + 4 pad (16B-aligned rows, odd in float4 units)
#define WS_STRIDE 36

__global__ void __launch_bounds__(256) input_proj_kernel(
    const float* __restrict__ x, const float* __restrict__ W_ih,
    const float* __restrict__ b_ih, const float* __restrict__ b_hh)
{
    __shared__ float xs[GA_BM * XS_STRIDE];
    __shared__ float ws[GA_BN * WS_STRIDE];
    const int tid = threadIdx.x;
    const int tx = tid & 15, ty = tid >> 4;
    const int m0 = blockIdx.x * GA_BM;
    const int n0 = blockIdx.y * GA_BN;

    unsigned long long acc[8][4];
    #pragma unroll
    for (int i = 0; i < 8; i++)
        #pragma unroll
        for (int j = 0; j < 4; j++) acc[i][j] = 0ull;

    const float4* xg = (const float4*)x;     // row = 75 float4 (K=300)
    const float4* wg = (const float4*)W_ih;  // row = 75 float4

    for (int kc = 0; kc < 10; kc++) {        // 10 chunks of 32 k (320, masked)
        #pragma unroll
        for (int l = 0; l < 4; l++) {        // x tile: 128 rows x 8 float4
            int idx = tid * 4 + l;
            int r = idx >> 3, c4 = idx & 7;
            int k4 = kc * 8 + c4;
            float4 v = make_float4(0.f, 0.f, 0.f, 0.f);
            if (k4 < 75) v = xg[(size_t)(m0 + r) * 75 + k4];
            *(float4*)&xs[r * XS_STRIDE + c4 * 4] = v;
        }
        #pragma unroll
        for (int l = 0; l < 2; l++) {        // w tile: 64 rows x 8 float4
            int idx = tid * 2 + l;
            int r = idx >> 3, c4 = idx & 7;
            int k4 = kc * 8 + c4;
            float4 v = make_float4(0.f, 0.f, 0.f, 0.f);
            if (k4 < 75) v = wg[(size_t)(n0 + r) * 75 + k4];
            *(float4*)&ws[r * WS_STRIDE + c4 * 4] = v;
        }
        __syncthreads();
        #pragma unroll
        for (int q = 0; q < 8; q++) {        // k-quad
            ulonglong2 wv[4], xv[8];
            #pragma unroll
            for (int j = 0; j < 4; j++)
                wv[j] = *(const ulonglong2*)&ws[(tx * 4 + j) * WS_STRIDE + q * 4];
            #pragma unroll
            for (int i = 0; i < 8; i++)
                xv[i] = *(const ulonglong2*)&xs[(ty * 8 + i) * XS_STRIDE + q * 4];
            #pragma unroll
            for (int i = 0; i < 8; i++)
                #pragma unroll
                for (int j = 0; j < 4; j++) {
                    fma2(acc[i][j], xv[i].x, wv[j].x);
                    fma2(acc[i][j], xv[i].y, wv[j].y);
                }
        }
        __syncthreads();
    }

    float bias[4];
    #pragma unroll
    for (int j = 0; j < 4; j++) {
        int n = n0 + tx * 4 + j;
        bias[j] = b_ih[n] + b_hh[n];
    }
    float4* outg = (float4*)g_xp;            // row = 64 float4 (H=256)
    #pragma unroll
    for (int i = 0; i < 8; i++) {
        float4 v;
        v.x = hsum2(acc[i][0]) + bias[0];
        v.y = hsum2(acc[i][1]) + bias[1];
        v.z = hsum2(acc[i][2]) + bias[2];
        v.w = hsum2(acc[i][3]) + bias[3];
        outg[(size_t)(m0 + ty * 8 + i) * 64 + (n0 >> 2) + tx] = v;
    }
}

// ---------------------------------------------------------------------------
// Kernel 2: persistent recurrence. 64 clusters of 2 CTAs (128 SMs).
// Cluster handles 4 batch rows. CTA rank r holds W_hh rows [128r,128r+128)
// in smem (padded stride 260 floats -> conflict-free LDS.128 across lanes),
// computes its half of h_new, writes it to both CTAs' ping-pong h buffers
// (DSMEM st.shared::cluster), barrier.cluster per step.
// 128 threads, thread tile = 2 h (ha, ha+64) x 2 batch, f32x2 K-packed.
// ---------------------------------------------------------------------------
#define W_STRIDE 260
#define R_SMEM_FLOATS (128 * W_STRIDE + 2 * 4 * HID)

__global__ void __cluster_dims__(2, 1, 1) __launch_bounds__(128, 1)
rnn_scan_kernel(const float* __restrict__ W_hh, const float* __restrict__ W_fc,
                const float* __restrict__ b_fc, float* __restrict__ out)
{
    extern __shared__ float sm[];
    float* Ws = sm;                     // 128 x 260
    float* hs = sm + 128 * W_STRIDE;    // 2 buffers x 4 batch x 256
    const int tid = threadIdx.x;
    uint32_t rank;
    asm("mov.u32 %0, %%cluster_ctarank;" : "=r"(rank));
    const int bbase = (blockIdx.x >> 1) * 4;

    // Load this CTA's half of W_hh into padded smem.
    {
        const float4* wg = (const float4*)(W_hh + (size_t)rank * 128 * HID);
        float4* ws4 = (float4*)Ws;
        for (int i = tid; i < 128 * 64; i += 128) {
            int r = i >> 6, c = i & 63;
            ws4[r * 65 + c] = wg[i];
        }
    }
    for (int i = tid; i < 2 * 4 * HID; i += 128) hs[i] = 0.0f;   // h0 = 0
    __syncthreads();
    // Peer must finish zeroing its buffers before our first DSMEM store.
    asm volatile("barrier.cluster.arrive.aligned;" ::: "memory");
    asm volatile("barrier.cluster.wait.aligned;" ::: "memory");

    const int ha = tid & 63;            // local h rows: ha, ha+64
    const int hb = ha + 64;
    const int b0 = (tid >> 6) << 1;     // local batch pair: {0,1} or {2,3}
    const int b1 = b0 + 1;
    const int hga = (int)rank * 128 + ha;   // global h indices
    const int hgb = hga + 64;

    const float* xp0 = g_xp + (size_t)(bbase + b0) * HID + hga;
    const float* xp1 = g_xp + (size_t)(bbase + b1) * HID + hga;

    uint32_t hs_u32 = (uint32_t)__cvta_generic_to_shared(hs);
    uint32_t peer_base;
    asm("mapa.shared::cluster.u32 %0, %1, %2;"
        : "=r"(peer_base) : "r"(hs_u32), "r"(1u - rank));

    const uint32_t off0 = (uint32_t)(b0 * HID + hga) * 4u;  // (b0, hga)
    const uint32_t off1 = (uint32_t)(b1 * HID + hga) * 4u;  // (b1, hga)
    const uint32_t off2 = (uint32_t)(b0 * HID + hgb) * 4u;  // (b0, hgb)
    const uint32_t off3 = (uint32_t)(b1 * HID + hgb) * 4u;  // (b1, hgb)

    const ulonglong2* wra = (const ulonglong2*)(Ws + ha * W_STRIDE);
    const ulonglong2* wrb = (const ulonglong2*)(Ws + hb * W_STRIDE);

    for (int t = 0; t < T_STEPS; t++) {
        const int p = t & 1;

        // xp loads for this step — issued up front, latency hidden by FMA loop
        float x_a0 = __ldg(xp0);
        float x_b0 = __ldg(xp0 + 64);
        float x_a1 = __ldg(xp1);
        float x_b1 = __ldg(xp1 + 64);
        xp0 += NBATCH * HID;
        xp1 += NBATCH * HID;

        const ulonglong2* hr0 = (const ulonglong2*)(hs + p * 1024 + b0 * HID);
        const ulonglong2* hr1 = (const ulonglong2*)(hs + p * 1024 + b1 * HID);

        unsigned long long aA0x = 0, aA0y = 0, aA1x = 0, aA1y = 0;
        unsigned long long aB0x = 0, aB0y = 0, aB1x = 0, aB1y = 0;
        #pragma unroll 16
        for (int q = 0; q < 64; q++) {          // 4 k per quad
            ulonglong2 wA = wra[q];
            ulonglong2 wB = wrb[q];
            ulonglong2 h0 = hr0[q];             // broadcast across warp
            ulonglong2 h1 = hr1[q];
            fma2(aA0x, wA.x, h0.x); fma2(aA0y, wA.y, h0.y);
            fma2(aA1x, wA.x, h1.x); fma2(aA1y, wA.y, h1.y);
            fma2(aB0x, wB.x, h0.x); fma2(aB0y, wB.y, h0.y);
            fma2(aB1x, wB.x, h1.x); fma2(aB1y, wB.y, h1.y);
        }
        float vA0 = fast_tanh(hsum2(aA0x) + hsum2(aA0y) + x_a0);
        float vA1 = fast_tanh(hsum2(aA1x) + hsum2(aA1y) + x_a1);
        float vB0 = fast_tanh(hsum2(aB0x) + hsum2(aB0y) + x_b0);
        float vB1 = fast_tanh(hsum2(aB1x) + hsum2(aB1y) + x_b1);

        float* hw = hs + (1 - p) * 1024;        // write buffer
        hw[b0 * HID + hga] = vA0;
        hw[b1 * HID + hga] = vA1;
        hw[b0 * HID + hgb] = vB0;
        hw[b1 * HID + hgb] = vB1;

        uint32_t pb = peer_base + (uint32_t)((1 - p) * 4096);
        asm volatile("st.shared::cluster.f32 [%0], %1;" :: "r"(pb + off0), "f"(vA0) : "memory");
        asm volatile("st.shared::cluster.f32 [%0], %1;" :: "r"(pb + off1), "f"(vA1) : "memory");
        asm volatile("st.shared::cluster.f32 [%0], %1;" :: "r"(pb + off2), "f"(vB0) : "memory");
        asm volatile("st.shared::cluster.f32 [%0], %1;" :: "r"(pb + off3), "f"(vB1) : "memory");

        // release my writes (local + DSMEM), acquire peer's
        asm volatile("barrier.cluster.arrive.aligned;" ::: "memory");
        asm volatile("barrier.cluster.wait.aligned;" ::: "memory");
    }

    // Tail: hT lives in buffer 0 (512 is even). Rank 0 emits log_softmax(hT@W_fcT+b).
    if (rank == 0) {
        const int w = tid >> 5;   // one warp per batch row (4 rows)
        const int l = tid & 31;
        const float* hT = hs + w * HID;
        float s0 = 0.f, s1 = 0.f;
        #pragma unroll
        for (int j = 0; j < 8; j++) {
            int h = l + 32 * j;
            float hv = hT[h];
            s0 += hv * W_fc[h];
            s1 += hv * W_fc[HID + h];
        }
        #pragma unroll
        for (int off = 16; off > 0; off >>= 1) {
            s0 += __shfl_xor_sync(0xffffffffu, s0, off);
            s1 += __shfl_xor_sync(0xffffffffu, s1, off);
        }
        if (l == 0) {
            float l0 = s0 + b_fc[0];
            float l1 = s1 + b_fc[1];
            float m  = fmaxf(l0, l1);
            float lse = m + logf(expf(l0 - m) + expf(l1 - m));
            int bg = bbase + w;
            out[bg * 2 + 0] = l0 - lse;
            out[bg * 2 + 1] = l1 - lse;
        }
    }
}

// ---------------------------------------------------------------------------
extern "C" void kernel_launch(void* const* d_in, const int* in_sizes, int n_in,
                              void* d_out, int out_size) {
    const float* x    = (const float*)d_in[0];
    const float* W_ih = (const float*)d_in[1];
    const float* W_hh = (const float*)d_in[2];
    const float* b_ih = (const float*)d_in[3];
    const float* b_hh = (const float*)d_in[4];
    const float* W_fc = (const float*)d_in[5];
    const float* b_fc = (const float*)d_in[6];
    float* out = (float*)d_out;

    dim3 g(T_STEPS * NBATCH / GA_BM, HID / GA_BN);   // (1024, 4)
    input_proj_kernel<<<g, 256>>>(x, W_ih, b_ih, b_hh);

    size_t smem = (size_t)R_SMEM_FLOATS * sizeof(float);  // 141312 B
    cudaFuncSetAttribute(rnn_scan_kernel,
                         cudaFuncAttributeMaxDynamicSharedMemorySize, (int)smem);
    rnn_scan_kernel<<<128, 128, smem>>>(W_hh, W_fc, b_fc, out);
}

// round 4
// speedup vs baseline: 1.0004x; 1.0004x over previous
#include <cuda_runtime.h>
#include <cstdint>
#include <math.h>

#define T_STEPS 512
#define NBATCH  256
#define IN_DIM  300
#define HID     256

// 134 MB scratch for the precomputed input projection xp[t][b][h]
__device__ float g_xp[T_STEPS * NBATCH * HID];

// ---------------------------------------------------------------------------
// packed f32x2 FMA helpers (ptxas never emits FFMA2 from C++; PTX-only)
// ---------------------------------------------------------------------------
__device__ __forceinline__ void fma2(unsigned long long& d,
                                     unsigned long long a,
                                     unsigned long long b) {
    asm("fma.rn.f32x2 %0, %1, %2, %0;" : "+l"(d) : "l"(a), "l"(b));
}
__device__ __forceinline__ float hsum2(unsigned long long v) {
    float lo = __uint_as_float((unsigned)v);
    float hi = __uint_as_float((unsigned)(v >> 32));
    return lo + hi;
}
__device__ __forceinline__ float fast_tanh(float z) {
    // tanh(z) = 1 - 2/(exp(2z)+1); exp overflow -> fdividef returns 0 -> 1.0 (correct)
    float e = __expf(2.0f * z);
    return 1.0f - __fdividef(2.0f, e + 1.0f);
}

// ---------------------------------------------------------------------------
// Kernel 1: xp[m][h] = x[m][:] . W_ih[h][:] + b_ih[h] + b_hh[h]
// M = 131072, K = 300 (pad-masked to 320), N = 256. fp32 with f32x2 K-packing.
// BM=128, BN=64, 256 threads, thread tile 8m x 4n.
// ---------------------------------------------------------------------------
#define GA_BM 128
#define GA_BN 64
#define XS_STRIDE 36   // 32 + 4 pad (16B-aligned rows, odd in float4 units)
#define WS_STRIDE 36

__global__ void __launch_bounds__(256) input_proj_kernel(
    const float* __restrict__ x, const float* __restrict__ W_ih,
    const float* __restrict__ b_ih, const float* __restrict__ b_hh)
{
    __shared__ float xs[GA_BM * XS_STRIDE];
    __shared__ float ws[GA_BN * WS_STRIDE];
    const int tid = threadIdx.x;
    const int tx = tid & 15, ty = tid >> 4;
    const int m0 = blockIdx.x * GA_BM;
    const int n0 = blockIdx.y * GA_BN;

    unsigned long long acc[8][4];
    #pragma unroll
    for (int i = 0; i < 8; i++)
        #pragma unroll
        for (int j = 0; j < 4; j++) acc[i][j] = 0ull;

    const float4* xg = (const float4*)x;     // row = 75 float4 (K=300)
    const float4* wg = (const float4*)W_ih;  // row = 75 float4

    for (int kc = 0; kc < 10; kc++) {        // 10 chunks of 32 k (320, masked)
        #pragma unroll
        for (int l = 0; l < 4; l++) {        // x tile: 128 rows x 8 float4
            int idx = tid * 4 + l;
            int r = idx >> 3, c4 = idx & 7;
            int k4 = kc * 8 + c4;
            float4 v = make_float4(0.f, 0.f, 0.f, 0.f);
            if (k4 < 75) v = xg[(size_t)(m0 + r) * 75 + k4];
            *(float4*)&xs[r * XS_STRIDE + c4 * 4] = v;
        }
        #pragma unroll
        for (int l = 0; l < 2; l++) {        // w tile: 64 rows x 8 float4
            int idx = tid * 2 + l;
            int r = idx >> 3, c4 = idx & 7;
            int k4 = kc * 8 + c4;
            float4 v = make_float4(0.f, 0.f, 0.f, 0.f);
            if (k4 < 75) v = wg[(size_t)(n0 + r) * 75 + k4];
            *(float4*)&ws[r * WS_STRIDE + c4 * 4] = v;
        }
        __syncthreads();
        #pragma unroll
        for (int q = 0; q < 8; q++) {        // k-quad
            ulonglong2 wv[4], xv[8];
            #pragma unroll
            for (int j = 0; j < 4; j++)
                wv[j] = *(const ulonglong2*)&ws[(tx * 4 + j) * WS_STRIDE + q * 4];
            #pragma unroll
            for (int i = 0; i < 8; i++)
                xv[i] = *(const ulonglong2*)&xs[(ty * 8 + i) * XS_STRIDE + q * 4];
            #pragma unroll
            for (int i = 0; i < 8; i++)
                #pragma unroll
                for (int j = 0; j < 4; j++) {
                    fma2(acc[i][j], xv[i].x, wv[j].x);
                    fma2(acc[i][j], xv[i].y, wv[j].y);
                }
        }
        __syncthreads();
    }

    float bias[4];
    #pragma unroll
    for (int j = 0; j < 4; j++) {
        int n = n0 + tx * 4 + j;
        bias[j] = b_ih[n] + b_hh[n];
    }
    float4* outg = (float4*)g_xp;            // row = 64 float4 (H=256)
    #pragma unroll
    for (int i = 0; i < 8; i++) {
        float4 v;
        v.x = hsum2(acc[i][0]) + bias[0];
        v.y = hsum2(acc[i][1]) + bias[1];
        v.z = hsum2(acc[i][2]) + bias[2];
        v.w = hsum2(acc[i][3]) + bias[3];
        outg[(size_t)(m0 + ty * 8 + i) * 64 + (n0 >> 2) + tx] = v;
    }
}

// ---------------------------------------------------------------------------
// Kernel 2: persistent recurrence. 64 clusters of 2 CTAs (128 SMs).
// Cluster handles 4 batch rows. CTA rank r holds W_hh rows [128r,128r+128)
// in smem (padded stride 260 floats -> conflict-free LDS.128 across lanes),
// computes its half of h_new, writes it to both CTAs' ping-pong h buffers
// (DSMEM st.shared::cluster), barrier.cluster per step.
// 128 threads, thread tile = 2 h (ha, ha+64) x 2 batch, f32x2 K-packed.
// ---------------------------------------------------------------------------
#define W_STRIDE 260
#define R_SMEM_FLOATS (128 * W_STRIDE + 2 * 4 * HID)

__global__ void __cluster_dims__(2, 1, 1) __launch_bounds__(128, 1)
rnn_scan_kernel(const float* __restrict__ W_hh, const float* __restrict__ W_fc,
                const float* __restrict__ b_fc, float* __restrict__ out)
{
    extern __shared__ float sm[];
    float* Ws = sm;                     // 128 x 260
    float* hs = sm + 128 * W_STRIDE;    // 2 buffers x 4 batch x 256
    const int tid = threadIdx.x;
    uint32_t rank;
    asm("mov.u32 %0, %%cluster_ctarank;" : "=r"(rank));
    const int bbase = (blockIdx.x >> 1) * 4;

    // Load this CTA's half of W_hh into padded smem.
    {
        const float4* wg = (const float4*)(W_hh + (size_t)rank * 128 * HID);
        float4* ws4 = (float4*)Ws;
        for (int i = tid; i < 128 * 64; i += 128) {
            int r = i >> 6, c = i & 63;
            ws4[r * 65 + c] = wg[i];
        }
    }
    for (int i = tid; i < 2 * 4 * HID; i += 128) hs[i] = 0.0f;   // h0 = 0
    __syncthreads();
    // Peer must finish zeroing its buffers before our first DSMEM store.
    asm volatile("barrier.cluster.arrive.aligned;" ::: "memory");
    asm volatile("barrier.cluster.wait.aligned;" ::: "memory");

    const int ha = tid & 63;            // local h rows: ha, ha+64
    const int hb = ha + 64;
    const int b0 = (tid >> 6) << 1;     // local batch pair: {0,1} or {2,3}
    const int b1 = b0 + 1;
    const int hga = (int)rank * 128 + ha;   // global h indices
    const int hgb = hga + 64;

    const float* xp0 = g_xp + (size_t)(bbase + b0) * HID + hga;
    const float* xp1 = g_xp + (size_t)(bbase + b1) * HID + hga;

    uint32_t hs_u32 = (uint32_t)__cvta_generic_to_shared(hs);
    uint32_t peer_base;
    asm("mapa.shared::cluster.u32 %0, %1, %2;"
        : "=r"(peer_base) : "r"(hs_u32), "r"(1u - rank));

    const uint32_t off0 = (uint32_t)(b0 * HID + hga) * 4u;  // (b0, hga)
    const uint32_t off1 = (uint32_t)(b1 * HID + hga) * 4u;  // (b1, hga)
    const uint32_t off2 = (uint32_t)(b0 * HID + hgb) * 4u;  // (b0, hgb)
    const uint32_t off3 = (uint32_t)(b1 * HID + hgb) * 4u;  // (b1, hgb)

    const ulonglong2* wra = (const ulonglong2*)(Ws + ha * W_STRIDE);
    const ulonglong2* wrb = (const ulonglong2*)(Ws + hb * W_STRIDE);

    for (int t = 0; t < T_STEPS; t++) {
        const int p = t & 1;

        // xp loads for this step — issued up front, latency hidden by FMA loop
        float x_a0 = __ldg(xp0);
        float x_b0 = __ldg(xp0 + 64);
        float x_a1 = __ldg(xp1);
        float x_b1 = __ldg(xp1 + 64);
        xp0 += NBATCH * HID;
        xp1 += NBATCH * HID;

        const ulonglong2* hr0 = (const ulonglong2*)(hs + p * 1024 + b0 * HID);
        const ulonglong2* hr1 = (const ulonglong2*)(hs + p * 1024 + b1 * HID);

        unsigned long long aA0x = 0, aA0y = 0, aA1x = 0, aA1y = 0;
        unsigned long long aB0x = 0, aB0y = 0, aB1x = 0, aB1y = 0;
        #pragma unroll 16
        for (int q = 0; q < 64; q++) {          // 4 k per quad
            ulonglong2 wA = wra[q];
            ulonglong2 wB = wrb[q];
            ulonglong2 h0 = hr0[q];             // broadcast across warp
            ulonglong2 h1 = hr1[q];
            fma2(aA0x, wA.x, h0.x); fma2(aA0y, wA.y, h0.y);
            fma2(aA1x, wA.x, h1.x); fma2(aA1y, wA.y, h1.y);
            fma2(aB0x, wB.x, h0.x); fma2(aB0y, wB.y, h0.y);
            fma2(aB1x, wB.x, h1.x); fma2(aB1y, wB.y, h1.y);
        }
        float vA0 = fast_tanh(hsum2(aA0x) + hsum2(aA0y) + x_a0);
        float vA1 = fast_tanh(hsum2(aA1x) + hsum2(aA1y) + x_a1);
        float vB0 = fast_tanh(hsum2(aB0x) + hsum2(aB0y) + x_b0);
        float vB1 = fast_tanh(hsum2(aB1x) + hsum2(aB1y) + x_b1);

        float* hw = hs + (1 - p) * 1024;        // write buffer
        hw[b0 * HID + hga] = vA0;
        hw[b1 * HID + hga] = vA1;
        hw[b0 * HID + hgb] = vB0;
        hw[b1 * HID + hgb] = vB1;

        uint32_t pb = peer_base + (uint32_t)((1 - p) * 4096);
        asm volatile("st.shared::cluster.f32 [%0], %1;" :: "r"(pb + off0), "f"(vA0) : "memory");
        asm volatile("st.shared::cluster.f32 [%0], %1;" :: "r"(pb + off1), "f"(vA1) : "memory");
        asm volatile("st.shared::cluster.f32 [%0], %1;" :: "r"(pb + off2), "f"(vB0) : "memory");
        asm volatile("st.shared::cluster.f32 [%0], %1;" :: "r"(pb + off3), "f"(vB1) : "memory");

        // release my writes (local + DSMEM), acquire peer's
        asm volatile("barrier.cluster.arrive.aligned;" ::: "memory");
        asm volatile("barrier.cluster.wait.aligned;" ::: "memory");
    }

    // Tail: hT lives in buffer 0 (512 is even). Rank 0 emits log_softmax(hT@W_fcT+b).
    if (rank == 0) {
        const int w = tid >> 5;   // one warp per batch row (4 rows)
        const int l = tid & 31;
        const float* hT = hs + w * HID;
        float s0 = 0.f, s1 = 0.f;
        #pragma unroll
        for (int j = 0; j < 8; j++) {
            int h = l + 32 * j;
            float hv = hT[h];
            s0 += hv * W_fc[h];
            s1 += hv * W_fc[HID + h];
        }
        #pragma unroll
        for (int off = 16; off > 0; off >>= 1) {
            s0 += __shfl_xor_sync(0xffffffffu, s0, off);
            s1 += __shfl_xor_sync(0xffffffffu, s1, off);
        }
        if (l == 0) {
            float l0 = s0 + b_fc[0];
            float l1 = s1 + b_fc[1];
            float m  = fmaxf(l0, l1);
            float lse = m + logf(expf(l0 - m) + expf(l1 - m));
            int bg = bbase + w;
            out[bg * 2 + 0] = l0 - lse;
            out[bg * 2 + 1] = l1 - lse;
        }
    }
}

// ---------------------------------------------------------------------------
extern "C" void kernel_launch(void* const* d_in, const int* in_sizes, int n_in,
                              void* d_out, int out_size) {
    const float* x    = (const float*)d_in[0];
    const float* W_ih = (const float*)d_in[1];
    const float* W_hh = (const float*)d_in[2];
    const float* b_ih = (const float*)d_in[3];
    const float* b_hh = (const float*)d_in[4];
    const float* W_fc = (const float*)d_in[5];
    const float* b_fc = (const float*)d_in[6];
    float* out = (float*)d_out;

    dim3 g(T_STEPS * NBATCH / GA_BM, HID / GA_BN);   // (1024, 4)
    input_proj_kernel<<<g, 256>>>(x, W_ih, b_ih, b_hh);

    size_t smem = (size_t)R_SMEM_FLOATS * sizeof(float);  // 141312 B
    cudaFuncSetAttribute(rnn_scan_kernel,
                         cudaFuncAttributeMaxDynamicSharedMemorySize, (int)smem);
    rnn_scan_kernel<<<128, 128, smem>>>(W_hh, W_fc, b_fc, out);
}

// round 6
// speedup vs baseline: 1.2169x; 1.2164x over previous
#include <cuda_runtime.h>
#include <cstdint>
#include <math.h>

#define T_STEPS 512
#define NBATCH  256
#define IN_DIM  300
#define HID     256

// 134 MB scratch for the precomputed input projection xp[t][b][h]
__device__ float g_xp[T_STEPS * NBATCH * HID];

// ---------------------------------------------------------------------------
// helpers
// ---------------------------------------------------------------------------
__device__ __forceinline__ uint32_t smem_u32(const void* p) {
    uint32_t a;
    asm("{ .reg .u64 t; cvta.to.shared.u64 t, %1; cvt.u32.u64 %0, t; }"
        : "=r"(a) : "l"(p));
    return a;
}
__device__ __forceinline__ void fma2(unsigned long long& d,
                                     unsigned long long a,
                                     unsigned long long b) {
    asm("fma.rn.f32x2 %0, %1, %2, %0;" : "+l"(d) : "l"(a), "l"(b));
}
__device__ __forceinline__ float hsum2(unsigned long long v) {
    return __uint_as_float((unsigned)v) + __uint_as_float((unsigned)(v >> 32));
}
__device__ __forceinline__ float fast_tanh(float z) {
    float e = __expf(2.0f * z);
    return 1.0f - __fdividef(2.0f, e + 1.0f);
}
__device__ __forceinline__ void mbar_wait_cluster(uint32_t mbar, uint32_t parity) {
    uint32_t done;
    asm volatile(
        "{ .reg .pred p;\n"
        "  mbarrier.try_wait.parity.acquire.cluster.shared::cta.b64 p, [%1], %2;\n"
        "  selp.b32 %0, 1, 0, p; }"
        : "=r"(done) : "r"(mbar), "r"(parity) : "memory");
    if (!done) {
        asm volatile(
            "{ .reg .pred P;\n"
            "LW%=:\n"
            "  mbarrier.try_wait.parity.acquire.cluster.shared::cta.b64 P, [%0], %1, 0x989680;\n"
            "  @P bra.uni LD%=;\n"
            "  bra.uni LW%=;\n"
            "LD%=: }"
            :: "r"(mbar), "r"(parity) : "memory");
    }
}

// ---------------------------------------------------------------------------
// Kernel 1: xp[m][h] = x[m][:] . W_ih[h][:] + b_ih[h] + b_hh[h]
// M = 131072, K = 300 (pad-masked to 320), N = 256. fp32 with f32x2 K-packing.
// BM=128, BN=64, 256 threads, thread tile 8m x 4n.  (proven R2 kernel)
// ---------------------------------------------------------------------------
#define GA_BM 128
#define GA_BN 64
#define XS_STRIDE 36
#define WS_STRIDE 36

__global__ void __launch_bounds__(256, 2) input_proj_kernel(
    const float* __restrict__ x, const float* __restrict__ W_ih,
    const float* __restrict__ b_ih, const float* __restrict__ b_hh)
{
    __shared__ float xs[GA_BM * XS_STRIDE];
    __shared__ float ws[GA_BN * WS_STRIDE];
    const int tid = threadIdx.x;
    const int tx = tid & 15, ty = tid >> 4;
    const int m0 = blockIdx.x * GA_BM;
    const int n0 = blockIdx.y * GA_BN;

    unsigned long long acc[8][4];
    #pragma unroll
    for (int i = 0; i < 8; i++)
        #pragma unroll
        for (int j = 0; j < 4; j++) acc[i][j] = 0ull;

    const float4* xg = (const float4*)x;     // row = 75 float4 (K=300)
    const float4* wg = (const float4*)W_ih;  // row = 75 float4

    for (int kc = 0; kc < 10; kc++) {
        #pragma unroll
        for (int l = 0; l < 4; l++) {        // x tile: 128 rows x 8 float4
            int idx = tid * 4 + l;
            int r = idx >> 3, c4 = idx & 7;
            int k4 = kc * 8 + c4;
            float4 v = make_float4(0.f, 0.f, 0.f, 0.f);
            if (k4 < 75) v = xg[(size_t)(m0 + r) * 75 + k4];
            *(float4*)&xs[r * XS_STRIDE + c4 * 4] = v;
        }
        #pragma unroll
        for (int l = 0; l < 2; l++) {        // w tile: 64 rows x 8 float4
            int idx = tid * 2 + l;
            int r = idx >> 3, c4 = idx & 7;
            int k4 = kc * 8 + c4;
            float4 v = make_float4(0.f, 0.f, 0.f, 0.f);
            if (k4 < 75) v = wg[(size_t)(n0 + r) * 75 + k4];
            *(float4*)&ws[r * WS_STRIDE + c4 * 4] = v;
        }
        __syncthreads();
        #pragma unroll
        for (int q = 0; q < 8; q++) {        // k-quad
            ulonglong2 wv[4], xv[8];
            #pragma unroll
            for (int j = 0; j < 4; j++)
                wv[j] = *(const ulonglong2*)&ws[(tx * 4 + j) * WS_STRIDE + q * 4];
            #pragma unroll
            for (int i = 0; i < 8; i++)
                xv[i] = *(const ulonglong2*)&xs[(ty * 8 + i) * XS_STRIDE + q * 4];
            #pragma unroll
            for (int i = 0; i < 8; i++)
                #pragma unroll
                for (int j = 0; j < 4; j++) {
                    fma2(acc[i][j], xv[i].x, wv[j].x);
                    fma2(acc[i][j], xv[i].y, wv[j].y);
                }
        }
        __syncthreads();
    }

    float bias[4];
    #pragma unroll
    for (int j = 0; j < 4; j++) {
        int n = n0 + tx * 4 + j;
        bias[j] = b_ih[n] + b_hh[n];
    }
    float4* outg = (float4*)g_xp;            // row = 64 float4 (H=256)
    #pragma unroll
    for (int i = 0; i < 8; i++) {
        float4 v;
        v.x = hsum2(acc[i][0]) + bias[0];
        v.y = hsum2(acc[i][1]) + bias[1];
        v.z = hsum2(acc[i][2]) + bias[2];
        v.w = hsum2(acc[i][3]) + bias[3];
        outg[(size_t)(m0 + ty * 8 + i) * 64 + (n0 >> 2) + tx] = v;
    }
}

// ---------------------------------------------------------------------------
// Kernel 2: persistent recurrence. 64 clusters x 2 CTAs, 4 batch / cluster.
// 256 threads: thread = (h-row ha in this CTA's half, K-half kh).
// W_hh[row][kh*128..+128) lives in 64 f32x2 REGISTERS (loaded once).
// Per step: broadcast h LDS.128 + register FMA2; K-halves combine via a
// parity-double-buffered smem reduce; halves exchanged across the cluster by
// DSMEM stores + dual release-arrive (peer mbar + local mbar, count=256) and
// an acquire try_wait — no barrier.cluster (no UCGABAR/L1-flush) in the loop.
// ---------------------------------------------------------------------------
__global__ void __cluster_dims__(2, 1, 1) __launch_bounds__(256, 1)
rnn_scan_kernel(const float* __restrict__ W_hh, const float* __restrict__ W_fc,
                const float* __restrict__ b_fc, float* __restrict__ out)
{
    __shared__ __align__(16) float hs[2 * 4 * HID];   // ping-pong h, 4 batches
    __shared__ float red[2][4 * 128];                 // K-half partials (x2 parity)
    __shared__ __align__(8) unsigned long long mb;

    const int tid = threadIdx.x;
    uint32_t rank;
    asm("mov.u32 %0, %%cluster_ctarank;" : "=r"(rank));
    const int bbase = (blockIdx.x >> 1) * 4;
    const int ha = tid & 127, kh = tid >> 7;          // kh warp-uniform
    const int grow = (int)rank * 128 + ha;            // global h row

    // W_hh[grow][kh*128 .. +128) -> 64 packed-f32x2 registers
    unsigned long long w[64];
    {
        const unsigned long long* Wr =
            (const unsigned long long*)(W_hh + (size_t)grow * HID + kh * 128);
        #pragma unroll
        for (int j = 0; j < 64; j++) w[j] = Wr[j];
    }
    for (int i = tid; i < 2 * 4 * HID; i += 256) hs[i] = 0.0f;
    const uint32_t mbar = smem_u32(&mb);
    if (tid == 0)
        asm volatile("mbarrier.init.shared.b64 [%0], %1;" :: "r"(mbar), "r"(256) : "memory");
    __syncthreads();
    // one-time: peer mbar init + hs zero visible before any DSMEM traffic
    asm volatile("barrier.cluster.arrive.aligned;" ::: "memory");
    asm volatile("barrier.cluster.wait.aligned;" ::: "memory");

    uint32_t peer_mbar, peer_hs;
    asm("mapa.shared::cluster.u32 %0, %1, %2;" : "=r"(peer_mbar) : "r"(mbar), "r"(1u - rank));
    asm("mapa.shared::cluster.u32 %0, %1, %2;" : "=r"(peer_hs) : "r"(smem_u32(hs)), "r"(1u - rank));

    const float* xp = g_xp + (size_t)bbase * HID + grow;

    for (int t = 0; t < T_STEPS; t++) {
        const int p = t & 1;
        float xv0 = 0.f, xv1 = 0.f, xv2 = 0.f, xv3 = 0.f;
        if (kh == 0) {                        // warp-uniform branch
            xv0 = __ldg(xp);
            xv1 = __ldg(xp + HID);
            xv2 = __ldg(xp + 2 * HID);
            xv3 = __ldg(xp + 3 * HID);
        }
        xp += (size_t)NBATCH * HID;

        const float* rb = hs + p * 1024 + kh * 128;
        const ulonglong2* h0p = (const ulonglong2*)(rb);
        const ulonglong2* h1p = (const ulonglong2*)(rb + HID);
        const ulonglong2* h2p = (const ulonglong2*)(rb + 2 * HID);
        const ulonglong2* h3p = (const ulonglong2*)(rb + 3 * HID);

        unsigned long long a0x = 0, a0y = 0, a1x = 0, a1y = 0;
        unsigned long long a2x = 0, a2y = 0, a3x = 0, a3y = 0;
        #pragma unroll
        for (int jj = 0; jj < 32; jj++) {     // 4 k per iter, broadcast LDS
            ulonglong2 h0 = h0p[jj], h1 = h1p[jj], h2 = h2p[jj], h3 = h3p[jj];
            fma2(a0x, w[2 * jj], h0.x); fma2(a0y, w[2 * jj + 1], h0.y);
            fma2(a1x, w[2 * jj], h1.x); fma2(a1y, w[2 * jj + 1], h1.y);
            fma2(a2x, w[2 * jj], h2.x); fma2(a2y, w[2 * jj + 1], h2.y);
            fma2(a3x, w[2 * jj], h3.x); fma2(a3y, w[2 * jj + 1], h3.y);
        }
        float s0 = hsum2(a0x) + hsum2(a0y);
        float s1 = hsum2(a1x) + hsum2(a1y);
        float s2 = hsum2(a2x) + hsum2(a2y);
        float s3 = hsum2(a3x) + hsum2(a3y);

        if (kh == 1) {
            float* rd = red[p];
            rd[0 * 128 + ha] = s0; rd[1 * 128 + ha] = s1;
            rd[2 * 128 + ha] = s2; rd[3 * 128 + ha] = s3;
        }
        __syncthreads();                      // red ready
        if (kh == 0) {
            const float* rd = red[p];
            float v0 = fast_tanh(s0 + rd[0 * 128 + ha] + xv0);
            float v1 = fast_tanh(s1 + rd[1 * 128 + ha] + xv1);
            float v2 = fast_tanh(s2 + rd[2 * 128 + ha] + xv2);
            float v3 = fast_tanh(s3 + rd[3 * 128 + ha] + xv3);
            float* hw = hs + (1 - p) * 1024;
            hw[0 * HID + grow] = v0;
            hw[1 * HID + grow] = v1;
            hw[2 * HID + grow] = v2;
            hw[3 * HID + grow] = v3;
            uint32_t pb = peer_hs + (uint32_t)(((1 - p) * 1024 + grow) * 4);
            asm volatile("st.shared::cluster.f32 [%0], %1;" :: "r"(pb),        "f"(v0) : "memory");
            asm volatile("st.shared::cluster.f32 [%0], %1;" :: "r"(pb + 1024), "f"(v1) : "memory");
            asm volatile("st.shared::cluster.f32 [%0], %1;" :: "r"(pb + 2048), "f"(v2) : "memory");
            asm volatile("st.shared::cluster.f32 [%0], %1;" :: "r"(pb + 3072), "f"(v3) : "memory");
            // publish: release-arrive on peer's mbar (orders DSMEM stores) and
            // on our own (orders local hs stores for local waiters)
            asm volatile("mbarrier.arrive.release.cluster.shared::cluster.b64 _, [%0];"
                         :: "r"(peer_mbar) : "memory");
            asm volatile("mbarrier.arrive.shared.b64 _, [%0];"
                         :: "r"(mbar) : "memory");
        }
        mbar_wait_cluster(mbar, (uint32_t)(t & 1));   // both halves of h[t+1] ready
    }

    // Tail: hT in buffer 0 (512 even). Rank 0: log_softmax(hT @ W_fc^T + b).
    if (rank == 0 && tid < 128) {
        const int wv = tid >> 5, l = tid & 31;        // warp = batch row
        const float* hT = hs + wv * HID;
        float t0 = 0.f, t1 = 0.f;
        #pragma unroll
        for (int j = 0; j < 8; j++) {
            int h = l + 32 * j;
            float hv = hT[h];
            t0 += hv * W_fc[h];
            t1 += hv * W_fc[HID + h];
        }
        #pragma unroll
        for (int off = 16; off > 0; off >>= 1) {
            t0 += __shfl_xor_sync(0xffffffffu, t0, off);
            t1 += __shfl_xor_sync(0xffffffffu, t1, off);
        }
        if (l == 0) {
            float l0 = t0 + b_fc[0];
            float l1 = t1 + b_fc[1];
            float m = fmaxf(l0, l1);
            float lse = m + logf(expf(l0 - m) + expf(l1 - m));
            int bg = bbase + wv;
            out[bg * 2 + 0] = l0 - lse;
            out[bg * 2 + 1] = l1 - lse;
        }
    }
    if (tid == 0)
        asm volatile("mbarrier.inval.shared.b64 [%0];" :: "r"(mbar) : "memory");
}

// ---------------------------------------------------------------------------
extern "C" void kernel_launch(void* const* d_in, const int* in_sizes, int n_in,
                              void* d_out, int out_size) {
    const float* x    = (const float*)d_in[0];
    const float* W_ih = (const float*)d_in[1];
    const float* W_hh = (const float*)d_in[2];
    const float* b_ih = (const float*)d_in[3];
    const float* b_hh = (const float*)d_in[4];
    const float* W_fc = (const float*)d_in[5];
    const float* b_fc = (const float*)d_in[6];
    float* out = (float*)d_out;

    dim3 g(T_STEPS * NBATCH / GA_BM, HID / GA_BN);   // (1024, 4)
    input_proj_kernel<<<g, 256>>>(x, W_ih, b_ih, b_hh);

    rnn_scan_kernel<<<128, 256>>>(W_hh, W_fc, b_fc, out);
}

// round 12
// speedup vs baseline: 1.8139x; 1.4906x over previous
#include <cuda_runtime.h>
#include <cuda_bf16.h>
#include <cstdint>
#include <math.h>

#define T_STEPS 512
#define NBATCH  256
#define HID     256

// 134 MB scratch for the precomputed input projection xp[t][b][h]
__device__ float g_xp[T_STEPS * NBATCH * HID];

// ---------------------------------------------------------------------------
// helpers
// ---------------------------------------------------------------------------
__device__ __forceinline__ uint32_t smem_u32(const void* p) {
    uint32_t a;
    asm("{ .reg .u64 t; cvta.to.shared.u64 t, %1; cvt.u32.u64 %0, t; }"
        : "=r"(a) : "l"(p));
    return a;
}
__device__ __forceinline__ void fma2(unsigned long long& d,
                                     unsigned long long a,
                                     unsigned long long b) {
    asm("fma.rn.f32x2 %0, %1, %2, %0;" : "+l"(d) : "l"(a), "l"(b));
}
__device__ __forceinline__ float hsum2(unsigned long long v) {
    return __uint_as_float((unsigned)v) + __uint_as_float((unsigned)(v >> 32));
}
__device__ __forceinline__ float fast_tanh(float z) {
    float e = __expf(2.0f * z);
    return 1.0f - __fdividef(2.0f, e + 1.0f);
}
// pack two f32 -> bf16x2 (first arg -> low half = lower k index)
__device__ __forceinline__ uint32_t pack_bf16x2(float lo, float hi) {
    uint32_t r;
    asm("cvt.rn.bf16x2.f32 %0, %1, %2;" : "=r"(r) : "f"(hi), "f"(lo));
    return r;
}
__device__ __forceinline__ void mbar_wait_cluster(uint32_t mbar, uint32_t parity) {
    uint32_t done;
    asm volatile(
        "{ .reg .pred p;\n"
        "  mbarrier.try_wait.parity.acquire.cluster.shared::cta.b64 p, [%1], %2;\n"
        "  selp.b32 %0, 1, 0, p; }"
        : "=r"(done) : "r"(mbar), "r"(parity) : "memory");
    if (!done) {
        asm volatile(
            "{ .reg .pred P;\n"
            "LW%=:\n"
            "  mbarrier.try_wait.parity.acquire.cluster.shared::cta.b64 P, [%0], %1, 0x989680;\n"
            "  @P bra.uni LD%=;\n"
            "  bra.uni LW%=;\n"
            "LD%=: }"
            :: "r"(mbar), "r"(parity) : "memory");
    }
}

// ldmatrix x4 (16B-aligned per-lane addresses)
#define LDSM4(R, addr) \
    asm volatile("ldmatrix.sync.aligned.m8n8.x4.shared.b16 {%0,%1,%2,%3}, [%4];" \
        : "=r"((R)[0]), "=r"((R)[1]), "=r"((R)[2]), "=r"((R)[3]) : "r"(addr))

// D += A * B (bf16 -> f32)
__device__ __forceinline__ void mma_bf16(float* d, const uint32_t* a,
                                         uint32_t b0, uint32_t b1) {
    asm volatile(
        "mma.sync.aligned.m16n8k16.row.col.f32.bf16.bf16.f32 "
        "{%0,%1,%2,%3}, {%4,%5,%6,%7}, {%8,%9}, {%0,%1,%2,%3};"
        : "+f"(d[0]), "+f"(d[1]), "+f"(d[2]), "+f"(d[3])
        : "r"(a[0]), "r"(a[1]), "r"(a[2]), "r"(a[3]), "r"(b0), "r"(b1));
}

// split float4 into bf16 hi + bf16 residual-lo, store 8B each
__device__ __forceinline__ void cvt_store_split(char* hi_base, char* lo_base,
                                                float4 v, uint32_t off) {
    uint32_t h01 = pack_bf16x2(v.x, v.y), h23 = pack_bf16x2(v.z, v.w);
    float f0 = __uint_as_float(h01 << 16);
    float f1 = __uint_as_float(h01 & 0xffff0000u);
    float f2 = __uint_as_float(h23 << 16);
    float f3 = __uint_as_float(h23 & 0xffff0000u);
    uint32_t l01 = pack_bf16x2(v.x - f0, v.y - f1);
    uint32_t l23 = pack_bf16x2(v.z - f2, v.w - f3);
    *(uint2*)(hi_base + off) = make_uint2(h01, h23);
    *(uint2*)(lo_base + off) = make_uint2(l01, l23);
}

// ---------------------------------------------------------------------------
// Kernel 1: xp = x @ W_ih^T + (b_ih+b_hh) via mma.sync bf16x3 split.
// C tile 128x128, BK=32, 256 threads = 8 warps (warp tile 32m x 64n).
// smem tiles ALIGNED 16B (R7 fault fix) and padded to 40 bf16/row
// (80B pitch, 16B multiple -> every ldmatrix lane address stays 16B-aligned;
// 20r mod 32 distinct for 8 consecutive rows -> conflict-free).
// ---------------------------------------------------------------------------
#define APAD 40

__global__ void __launch_bounds__(256) input_proj_mma(
    const float* __restrict__ x, const float* __restrict__ W_ih,
    const float* __restrict__ b_ih, const float* __restrict__ b_hh)
{
    __shared__ __align__(16) __nv_bfloat16 sAhi[128 * APAD];
    __shared__ __align__(16) __nv_bfloat16 sAlo[128 * APAD];
    __shared__ __align__(16) __nv_bfloat16 sBhi[128 * APAD];
    __shared__ __align__(16) __nv_bfloat16 sBlo[128 * APAD];
    __shared__ float s_bias[128];

    const int tid = threadIdx.x, lane = tid & 31, wid = tid >> 5;
    const int wm = wid & 3, wn = wid >> 2;          // 4 m-warps x 2 n-warps
    const int m0 = blockIdx.x * 128, n0 = blockIdx.y * 128;

    if (tid < 128) s_bias[tid] = b_ih[n0 + tid] + b_hh[n0 + tid];

    float acc[2][8][4];
    #pragma unroll
    for (int i = 0; i < 2; i++)
        #pragma unroll
        for (int j = 0; j < 8; j++)
            #pragma unroll
            for (int q = 0; q < 4; q++) acc[i][j][q] = 0.0f;

    // ldmatrix per-lane addresses (constant across kc)
    const int lr = lane & 15, lc = (lane >> 4) << 3;
    uint32_t offA[2][2], offB[4][2];
    #pragma unroll
    for (int mf = 0; mf < 2; mf++)
        #pragma unroll
        for (int kf = 0; kf < 2; kf++)
            offA[mf][kf] = (uint32_t)(((wm * 32 + mf * 16 + lr) * APAD + kf * 16 + lc) * 2);
    #pragma unroll
    for (int n2 = 0; n2 < 4; n2++)
        #pragma unroll
        for (int kf = 0; kf < 2; kf++)
            offB[n2][kf] = (uint32_t)(((wn * 64 + n2 * 16 + lr) * APAD + kf * 16 + lc) * 2);

    const uint32_t aHi = smem_u32(sAhi), aLo = smem_u32(sAlo);
    const uint32_t bHi = smem_u32(sBhi), bLo = smem_u32(sBlo);

    const float4* xg = (const float4*)x;      // 75 float4 per row (K=300)
    const float4* wg = (const float4*)W_ih;

    for (int kc = 0; kc < 10; kc++) {         // K padded 300 -> 320
        #pragma unroll
        for (int l = 0; l < 4; l++) {         // A: 128 rows x 8 float4
            int idx = l * 256 + tid, r = idx >> 3, c4 = idx & 7, g4 = kc * 8 + c4;
            float4 v = make_float4(0.f, 0.f, 0.f, 0.f);
            if (g4 < 75) v = xg[(size_t)(m0 + r) * 75 + g4];
            cvt_store_split((char*)sAhi, (char*)sAlo, v, (uint32_t)(r * 80 + c4 * 8));
        }
        #pragma unroll
        for (int l = 0; l < 4; l++) {         // B: 128 W rows x 8 float4
            int idx = l * 256 + tid, r = idx >> 3, c4 = idx & 7, g4 = kc * 8 + c4;
            float4 v = make_float4(0.f, 0.f, 0.f, 0.f);
            if (g4 < 75) v = wg[(size_t)(n0 + r) * 75 + g4];
            cvt_store_split((char*)sBhi, (char*)sBlo, v, (uint32_t)(r * 80 + c4 * 8));
        }
        __syncthreads();

        uint32_t Ah[2][2][4], Al[2][2][4], Bf[4][2][4];
        #pragma unroll
        for (int mf = 0; mf < 2; mf++)
            #pragma unroll
            for (int kf = 0; kf < 2; kf++) {
                LDSM4(Ah[mf][kf], aHi + offA[mf][kf]);
                LDSM4(Al[mf][kf], aLo + offA[mf][kf]);
            }
        #pragma unroll
        for (int n2 = 0; n2 < 4; n2++)
            #pragma unroll
            for (int kf = 0; kf < 2; kf++)
                LDSM4(Bf[n2][kf], bHi + offB[n2][kf]);

        // hi*hi + lo*hi
        #pragma unroll
        for (int mf = 0; mf < 2; mf++)
            #pragma unroll
            for (int n2 = 0; n2 < 4; n2++)
                #pragma unroll
                for (int kf = 0; kf < 2; kf++) {
                    mma_bf16(acc[mf][n2 * 2 + 0], Ah[mf][kf], Bf[n2][kf][0], Bf[n2][kf][2]);
                    mma_bf16(acc[mf][n2 * 2 + 1], Ah[mf][kf], Bf[n2][kf][1], Bf[n2][kf][3]);
                    mma_bf16(acc[mf][n2 * 2 + 0], Al[mf][kf], Bf[n2][kf][0], Bf[n2][kf][2]);
                    mma_bf16(acc[mf][n2 * 2 + 1], Al[mf][kf], Bf[n2][kf][1], Bf[n2][kf][3]);
                }
        // hi*lo
        #pragma unroll
        for (int n2 = 0; n2 < 4; n2++)
            #pragma unroll
            for (int kf = 0; kf < 2; kf++)
                LDSM4(Bf[n2][kf], bLo + offB[n2][kf]);
        #pragma unroll
        for (int mf = 0; mf < 2; mf++)
            #pragma unroll
            for (int n2 = 0; n2 < 4; n2++)
                #pragma unroll
                for (int kf = 0; kf < 2; kf++) {
                    mma_bf16(acc[mf][n2 * 2 + 0], Ah[mf][kf], Bf[n2][kf][0], Bf[n2][kf][2]);
                    mma_bf16(acc[mf][n2 * 2 + 1], Ah[mf][kf], Bf[n2][kf][1], Bf[n2][kf][3]);
                }
        __syncthreads();
    }

    // Epilogue: c0,c1 -> (row g, cols 2t,2t+1); c2,c3 -> row g+8
    #pragma unroll
    for (int mf = 0; mf < 2; mf++)
        #pragma unroll
        for (int nf = 0; nf < 8; nf++) {
            int row = m0 + wm * 32 + mf * 16 + (lane >> 2);
            int colL = wn * 64 + nf * 8 + (lane & 3) * 2;
            float2 v;
            v.x = acc[mf][nf][0] + s_bias[colL];
            v.y = acc[mf][nf][1] + s_bias[colL + 1];
            *(float2*)&g_xp[(size_t)row * HID + n0 + colL] = v;
            v.x = acc[mf][nf][2] + s_bias[colL];
            v.y = acc[mf][nf][3] + s_bias[colL + 1];
            *(float2*)&g_xp[(size_t)(row + 8) * HID + n0 + colL] = v;
        }
}

// ---------------------------------------------------------------------------
// Kernel 2: persistent recurrence — PROVEN R6 version (839 us), unchanged.
// 64 clusters x 2 CTAs, 4 batch / cluster, 256 threads:
// thread = (h-row ha, K-half kh); W_hh slice in 64 f32x2 registers.
// DSMEM publish + dual release-arrive (peer + local mbar, count=256).
// ---------------------------------------------------------------------------
__global__ void __cluster_dims__(2, 1, 1) __launch_bounds__(256, 1)
rnn_scan_kernel(const float* __restrict__ W_hh, const float* __restrict__ W_fc,
                const float* __restrict__ b_fc, float* __restrict__ out)
{
    __shared__ __align__(16) float hs[2 * 4 * HID];   // ping-pong h, 4 batches
    __shared__ float red[2][4 * 128];                 // K-half partials (x2 parity)
    __shared__ __align__(8) unsigned long long mb;

    const int tid = threadIdx.x;
    uint32_t rank;
    asm("mov.u32 %0, %%cluster_ctarank;" : "=r"(rank));
    const int bbase = (blockIdx.x >> 1) * 4;
    const int ha = tid & 127, kh = tid >> 7;          // kh warp-uniform
    const int grow = (int)rank * 128 + ha;            // global h row

    // W_hh[grow][kh*128 .. +128) -> 64 packed-f32x2 registers
    unsigned long long w[64];
    {
        const unsigned long long* Wr =
            (const unsigned long long*)(W_hh + (size_t)grow * HID + kh * 128);
        #pragma unroll
        for (int j = 0; j < 64; j++) w[j] = Wr[j];
    }
    for (int i = tid; i < 2 * 4 * HID; i += 256) hs[i] = 0.0f;
    const uint32_t mbar = smem_u32(&mb);
    if (tid == 0)
        asm volatile("mbarrier.init.shared.b64 [%0], %1;" :: "r"(mbar), "r"(256) : "memory");
    __syncthreads();
    asm volatile("barrier.cluster.arrive.aligned;" ::: "memory");
    asm volatile("barrier.cluster.wait.aligned;" ::: "memory");

    uint32_t peer_mbar, peer_hs;
    asm("mapa.shared::cluster.u32 %0, %1, %2;" : "=r"(peer_mbar) : "r"(mbar), "r"(1u - rank));
    asm("mapa.shared::cluster.u32 %0, %1, %2;" : "=r"(peer_hs) : "r"(smem_u32(hs)), "r"(1u - rank));

    const float* xp = g_xp + (size_t)bbase * HID + grow;

    for (int t = 0; t < T_STEPS; t++) {
        const int p = t & 1;
        float xv0 = 0.f, xv1 = 0.f, xv2 = 0.f, xv3 = 0.f;
        if (kh == 0) {
            xv0 = __ldg(xp);
            xv1 = __ldg(xp + HID);
            xv2 = __ldg(xp + 2 * HID);
            xv3 = __ldg(xp + 3 * HID);
        }
        xp += (size_t)NBATCH * HID;

        const float* rb = hs + p * 1024 + kh * 128;
        const ulonglong2* h0p = (const ulonglong2*)(rb);
        const ulonglong2* h1p = (const ulonglong2*)(rb + HID);
        const ulonglong2* h2p = (const ulonglong2*)(rb + 2 * HID);
        const ulonglong2* h3p = (const ulonglong2*)(rb + 3 * HID);

        unsigned long long a0x = 0, a0y = 0, a1x = 0, a1y = 0;
        unsigned long long a2x = 0, a2y = 0, a3x = 0, a3y = 0;
        #pragma unroll
        for (int jj = 0; jj < 32; jj++) {     // 4 k per iter, broadcast LDS
            ulonglong2 h0 = h0p[jj], h1 = h1p[jj], h2 = h2p[jj], h3 = h3p[jj];
            fma2(a0x, w[2 * jj], h0.x); fma2(a0y, w[2 * jj + 1], h0.y);
            fma2(a1x, w[2 * jj], h1.x); fma2(a1y, w[2 * jj + 1], h1.y);
            fma2(a2x, w[2 * jj], h2.x); fma2(a2y, w[2 * jj + 1], h2.y);
            fma2(a3x, w[2 * jj], h3.x); fma2(a3y, w[2 * jj + 1], h3.y);
        }
        float s0 = hsum2(a0x) + hsum2(a0y);
        float s1 = hsum2(a1x) + hsum2(a1y);
        float s2 = hsum2(a2x) + hsum2(a2y);
        float s3 = hsum2(a3x) + hsum2(a3y);

        if (kh == 1) {
            float* rd = red[p];
            rd[0 * 128 + ha] = s0; rd[1 * 128 + ha] = s1;
            rd[2 * 128 + ha] = s2; rd[3 * 128 + ha] = s3;
        }
        __syncthreads();                      // red ready
        if (kh == 0) {
            const float* rd = red[p];
            float v0 = fast_tanh(s0 + rd[0 * 128 + ha] + xv0);
            float v1 = fast_tanh(s1 + rd[1 * 128 + ha] + xv1);
            float v2 = fast_tanh(s2 + rd[2 * 128 + ha] + xv2);
            float v3 = fast_tanh(s3 + rd[3 * 128 + ha] + xv3);
            float* hw = hs + (1 - p) * 1024;
            hw[0 * HID + grow] = v0;
            hw[1 * HID + grow] = v1;
            hw[2 * HID + grow] = v2;
            hw[3 * HID + grow] = v3;
            uint32_t pb = peer_hs + (uint32_t)(((1 - p) * 1024 + grow) * 4);
            asm volatile("st.shared::cluster.f32 [%0], %1;" :: "r"(pb),        "f"(v0) : "memory");
            asm volatile("st.shared::cluster.f32 [%0], %1;" :: "r"(pb + 1024), "f"(v1) : "memory");
            asm volatile("st.shared::cluster.f32 [%0], %1;" :: "r"(pb + 2048), "f"(v2) : "memory");
            asm volatile("st.shared::cluster.f32 [%0], %1;" :: "r"(pb + 3072), "f"(v3) : "memory");
            asm volatile("mbarrier.arrive.release.cluster.shared::cluster.b64 _, [%0];"
                         :: "r"(peer_mbar) : "memory");
            asm volatile("mbarrier.arrive.shared.b64 _, [%0];"
                         :: "r"(mbar) : "memory");
        }
        mbar_wait_cluster(mbar, (uint32_t)(t & 1));   // both halves of h[t+1] ready
    }

    // Tail: hT in buffer 0 (512 even). Rank 0: log_softmax(hT @ W_fc^T + b).
    if (rank == 0 && tid < 128) {
        const int wv = tid >> 5, l = tid & 31;        // warp = batch row
        const float* hT = hs + wv * HID;
        float t0 = 0.f, t1 = 0.f;
        #pragma unroll
        for (int j = 0; j < 8; j++) {
            int h = l + 32 * j;
            float hv = hT[h];
            t0 += hv * W_fc[h];
            t1 += hv * W_fc[HID + h];
        }
        #pragma unroll
        for (int off = 16; off > 0; off >>= 1) {
            t0 += __shfl_xor_sync(0xffffffffu, t0, off);
            t1 += __shfl_xor_sync(0xffffffffu, t1, off);
        }
        if (l == 0) {
            float l0 = t0 + b_fc[0];
            float l1 = t1 + b_fc[1];
            float m = fmaxf(l0, l1);
            float lse = m + logf(expf(l0 - m) + expf(l1 - m));
            int bg = bbase + wv;
            out[bg * 2 + 0] = l0 - lse;
            out[bg * 2 + 1] = l1 - lse;
        }
    }
    if (tid == 0)
        asm volatile("mbarrier.inval.shared.b64 [%0];" :: "r"(mbar) : "memory");
}

// ---------------------------------------------------------------------------
extern "C" void kernel_launch(void* const* d_in, const int* in_sizes, int n_in,
                              void* d_out, int out_size) {
    const float* x    = (const float*)d_in[0];
    const float* W_ih = (const float*)d_in[1];
    const float* W_hh = (const float*)d_in[2];
    const float* b_ih = (const float*)d_in[3];
    const float* b_hh = (const float*)d_in[4];
    const float* W_fc = (const float*)d_in[5];
    const float* b_fc = (const float*)d_in[6];
    float* out = (float*)d_out;

    dim3 g(T_STEPS * NBATCH / 128, HID / 128);   // (1024, 2)
    input_proj_mma<<<g, 256>>>(x, W_ih, b_ih, b_hh);

    rnn_scan_kernel<<<128, 256>>>(W_hh, W_fc, b_fc, out);
}